// round 2
// baseline (speedup 1.0000x reference)
#include <cuda_runtime.h>
#include <cstdint>

// ---------------------------------------------------------------------------
// Problem constants
// ---------------------------------------------------------------------------
#define BB   32
#define FEAT 512
#define SS   128
#define SP   (SS*SS)          // 16384 pixels
#define CD   8
#define KK   7

#define NBLK 256              // 8 blocks per batch
#define NTHR 256
#define PX   8                // pixels per thread (8*256*256 = 524288 = BB*SP)

// Output layout (floats), concatenated in reference return order
#define OFF_LOGM   ((size_t)0)                         // (8,32,1,128,128)
#define OFF_LOGS   ((size_t)4194304)                   // (8,32,1,128,128)
#define OFF_SEEDS  ((size_t)8388608)                   // (7,32,8)
#define OFF_COLOUR ((size_t)8390400)                   // (32,8,128,128)
#define OFF_DELTA  ((size_t)12584704)                  // (32,2,128,128)

// ---------------------------------------------------------------------------
// Globals (no allocations allowed). Barrier state is self-consistent across
// graph replays: count returns to 0 after every completed barrier, gen is
// read fresh at the start of each launch.
// ---------------------------------------------------------------------------
__device__ unsigned            g_bar_count;
__device__ volatile unsigned   g_bar_gen;
__device__ unsigned long long  g_slot[KK * BB];   // packed argmax per (step,batch)

// ---------------------------------------------------------------------------
// f32x2 helpers (Blackwell packed fp32 — 2x FFMA throughput)
// ---------------------------------------------------------------------------
__device__ __forceinline__ unsigned long long pk2(float a, float b) {
    unsigned long long r;
    asm("mov.b64 %0, {%1,%2};" : "=l"(r) : "f"(a), "f"(b));
    return r;
}
__device__ __forceinline__ void upk2(unsigned long long v, float& a, float& b) {
    asm("mov.b64 {%0,%1}, %2;" : "=f"(a), "=f"(b) : "l"(v));
}
__device__ __forceinline__ unsigned long long ffma2(unsigned long long a,
                                                    unsigned long long b,
                                                    unsigned long long c) {
    unsigned long long r;
    asm("fma.rn.f32x2 %0, %1, %2, %3;" : "=l"(r) : "l"(a), "l"(b), "l"(c));
    return r;
}

// ---------------------------------------------------------------------------
// Grid-wide barrier (all NBLK blocks are resident by construction:
// launch_bounds(256,2) -> <=128 regs, 2 blocks/SM * 148 SMs = 296 >= 256)
// ---------------------------------------------------------------------------
__device__ __forceinline__ void grid_sync(unsigned& gen) {
    __syncthreads();
    if (threadIdx.x == 0) {
        __threadfence();
        if (atomicAdd(&g_bar_count, 1u) == NBLK - 1) {
            g_bar_count = 0;
            __threadfence();
            g_bar_gen = gen + 1;
        } else {
            while (g_bar_gen == gen) __nanosleep(32);
        }
        __threadfence();
    }
    __syncthreads();
    gen++;
}

// ---------------------------------------------------------------------------
// Block-level packed-argmax reduce + atomic publish
// key = (bits(pp) << 32) | (16383 - pixel_idx); ties -> lowest index (jnp.argmax)
// ---------------------------------------------------------------------------
__device__ __forceinline__ void publish_argmax(unsigned long long key,
                                               unsigned long long* slot,
                                               unsigned long long* s_red,
                                               int tid) {
    #pragma unroll
    for (int o = 16; o; o >>= 1) {
        unsigned long long other = __shfl_down_sync(0xffffffffu, key, o);
        key = key > other ? key : other;
    }
    if ((tid & 31) == 0) s_red[tid >> 5] = key;
    __syncthreads();
    if (tid < 32) {
        unsigned long long v = (tid < 8) ? s_red[tid] : 0ull;
        #pragma unroll
        for (int o = 4; o; o >>= 1) {
            unsigned long long other = __shfl_down_sync(0xffffffffu, v, o);
            v = v > other ? v : other;
        }
        if (tid == 0) atomicMax(slot, v);
    }
    __syncthreads();
}

#define MMA_O(o, wv)                                     \
    acc[(o)*4+0] = ffma2(p01, (wv), acc[(o)*4+0]);       \
    acc[(o)*4+1] = ffma2(p23, (wv), acc[(o)*4+1]);       \
    acc[(o)*4+2] = ffma2(p45, (wv), acc[(o)*4+2]);       \
    acc[(o)*4+3] = ffma2(p67, (wv), acc[(o)*4+3]);

// ---------------------------------------------------------------------------
// The whole problem in one kernel: GEMM -> barrier -> 7 fused SBP steps.
// Colour lives in registers across all steps.
// ---------------------------------------------------------------------------
__global__ void __launch_bounds__(NTHR, 2)
fused_kernel(const float* __restrict__ features,
             const float* __restrict__ rand_pixel,
             const float* __restrict__ conv_w,
             const float* __restrict__ conv_b,
             const float* __restrict__ gate,
             const float* __restrict__ log_sigma,
             const float* __restrict__ uv,
             float* __restrict__ out) {
    __shared__ float2 wt2[FEAT * CD];          // duplicated weight pairs, 32 KB
    __shared__ float s_seed[CD];
    __shared__ unsigned long long s_red[8];

    int tid = threadIdx.x;
    unsigned gen = g_bar_gen;                  // stable until all blocks arrive

    // Stage weights (transposed + duplicated for f32x2)
    for (int i = tid; i < FEAT * CD; i += NTHR) {
        int c = i >> 3, o = i & 7;
        float w = conv_w[o * FEAT + c];
        wt2[c * CD + o] = make_float2(w, w);
    }
    // Reset argmax slots for this replay
    if (blockIdx.x == 0 && tid < KK * BB) g_slot[tid] = 0ull;

    int b   = blockIdx.x >> 3;
    int pix = (int)(blockIdx.x & 7) * (NTHR * PX) + tid * PX;

    grid_sync(gen);                            // slots zeroed, weights staged

    // rand values for this thread's 8 pixels (kept in regs for all steps)
    const float4* rp = (const float4*)(rand_pixel + (size_t)b * SP + pix);
    float4 r0 = rp[0], r1 = rp[1];
    float ra[PX] = {r0.x, r0.y, r0.z, r0.w, r1.x, r1.y, r1.z, r1.w};

    // step-0 argmax: scope == 1 -> pp == rand_pixel
    {
        float vmax = -1.0f; int imax = 0;
        #pragma unroll
        for (int j = 0; j < PX; j++)
            if (ra[j] > vmax) { vmax = ra[j]; imax = pix + j; }
        unsigned long long key =
            (((unsigned long long)__float_as_uint(vmax)) << 32) |
            (unsigned long long)(unsigned)(16383 - imax);
        publish_argmax(key, &g_slot[b], s_red, tid);
    }

    // ---------------- GEMM phase: 8 outputs x 8 pixels per thread ----------
    const float* fb = features + (size_t)b * FEAT * SP + pix;
    unsigned long long acc[32];
    #pragma unroll
    for (int i = 0; i < 32; i++) acc[i] = 0ull;

    #pragma unroll 2
    for (int c = 0; c < FEAT; c++) {
        const float4* fp = (const float4*)(fb + (size_t)c * SP);
        float4 fv0 = __ldcs(fp);
        float4 fv1 = __ldcs(fp + 1);
        unsigned long long p01 = pk2(fv0.x, fv0.y);
        unsigned long long p23 = pk2(fv0.z, fv0.w);
        unsigned long long p45 = pk2(fv1.x, fv1.y);
        unsigned long long p67 = pk2(fv1.z, fv1.w);
        const ulonglong2* wr = (const ulonglong2*)(wt2 + c * CD);
        ulonglong2 wA = wr[0], wB = wr[1], wC = wr[2], wD = wr[3];
        MMA_O(0, wA.x) MMA_O(1, wA.y) MMA_O(2, wB.x) MMA_O(3, wB.y)
        MMA_O(4, wC.x) MMA_O(5, wC.y) MMA_O(6, wD.x) MMA_O(7, wD.y)
    }

    // Epilogue: x = gate*(acc+b); colour = x+uv (kept in regs); write colour+delta
    float g = gate[0];
    float col[CD][PX];
    #pragma unroll
    for (int o = 0; o < CD; o++) {
        float a[PX];
        upk2(acc[o * 4 + 0], a[0], a[1]);
        upk2(acc[o * 4 + 1], a[2], a[3]);
        upk2(acc[o * 4 + 2], a[4], a[5]);
        upk2(acc[o * 4 + 3], a[6], a[7]);
        float bo = conv_b[o];
        float x[PX];
        #pragma unroll
        for (int j = 0; j < PX; j++) x[j] = g * (a[j] + bo);
        const float4* uvp = (const float4*)(uv + (size_t)o * SP + pix);
        float4 u0 = uvp[0], u1 = uvp[1];
        col[o][0] = x[0] + u0.x; col[o][1] = x[1] + u0.y;
        col[o][2] = x[2] + u0.z; col[o][3] = x[3] + u0.w;
        col[o][4] = x[4] + u1.x; col[o][5] = x[5] + u1.y;
        col[o][6] = x[6] + u1.z; col[o][7] = x[7] + u1.w;
        float* cp = out + OFF_COLOUR + (size_t)b * (CD * SP) + (size_t)o * SP + pix;
        *(float4*)cp       = make_float4(col[o][0], col[o][1], col[o][2], col[o][3]);
        *(float4*)(cp + 4) = make_float4(col[o][4], col[o][5], col[o][6], col[o][7]);
        if (o >= 6) {
            float* dp = out + OFF_DELTA + (size_t)b * (2 * SP) + (size_t)(o - 6) * SP + pix;
            *(float4*)dp       = make_float4(x[0], x[1], x[2], x[3]);
            *(float4*)(dp + 4) = make_float4(x[4], x[5], x[6], x[7]);
        }
    }

    grid_sync(gen);                 // colour globally visible, slot[0] final

    // ---------------- 7 fused SBP steps ------------------------------------
    float inv_sigma = 1.0f / expf(log_sigma[0]);
    float ls[PX];
    #pragma unroll
    for (int j = 0; j < PX; j++) ls[j] = 0.0f;

    for (int k = 0; k < KK; k++) {
        unsigned long long slotv = __ldcg(&g_slot[k * BB + b]);
        int idx = 16383 - (int)(unsigned)(slotv & 0xffffffffull);

        if (tid < CD) {
            float sv = __ldcg(out + OFF_COLOUR + (size_t)b * (CD * SP) +
                              (size_t)tid * SP + idx);
            s_seed[tid] = sv;
            if ((blockIdx.x & 7) == 0)
                out[OFF_SEEDS + ((size_t)k * BB + b) * CD + tid] = sv;
        }
        __syncthreads();
        float sd[CD];
        #pragma unroll
        for (int c = 0; c < CD; c++) sd[c] = s_seed[c];
        __syncthreads();            // protect s_seed before next step's write

        float d2[PX];
        #pragma unroll
        for (int j = 0; j < PX; j++) d2[j] = 0.0f;
        #pragma unroll
        for (int c = 0; c < CD; c++) {
            #pragma unroll
            for (int j = 0; j < PX; j++) {
                float d = col[c][j] - sd[c];
                d2[j] = fmaf(d, d, d2[j]);
            }
        }

        float lm[PX], nls[PX];
        #pragma unroll
        for (int j = 0; j < PX; j++) {
            float z    = d2[j] * inv_sigma;
            float araw = expf(-z);
            float alpha = araw, la = -z;
            if (araw < 0.01f) { alpha = 0.01f; la = -4.6051702f;  }   // log(0.01)
            if (araw > 0.99f) { alpha = 0.99f; la = -0.01005034f; }   // log(0.99)
            lm[j]  = ls[j] + la;
            nls[j] = ls[j] + log1pf(-alpha);
        }

        size_t pbase = (size_t)b * SP + pix;
        float* lmp  = out + OFF_LOGM + (size_t)k * (BB * SP) + pbase;
        float* lsp  = out + OFF_LOGS + (size_t)(k + 1) * (BB * SP) + pbase;
        __stcs((float4*)lmp,       make_float4(lm[0], lm[1], lm[2], lm[3]));
        __stcs((float4*)(lmp + 4), make_float4(lm[4], lm[5], lm[6], lm[7]));
        __stcs((float4*)lsp,       make_float4(nls[0], nls[1], nls[2], nls[3]));
        __stcs((float4*)(lsp + 4), make_float4(nls[4], nls[5], nls[6], nls[7]));
        if (k == 0) {
            float* z0 = out + OFF_LOGS + pbase;
            __stcs((float4*)z0,       make_float4(0.f, 0.f, 0.f, 0.f));
            __stcs((float4*)(z0 + 4), make_float4(0.f, 0.f, 0.f, 0.f));
        }
        if (k == KK - 1) {
            float* fm = out + OFF_LOGM + (size_t)KK * (BB * SP) + pbase;
            __stcs((float4*)fm,       make_float4(nls[0], nls[1], nls[2], nls[3]));
            __stcs((float4*)(fm + 4), make_float4(nls[4], nls[5], nls[6], nls[7]));
        }

        #pragma unroll
        for (int j = 0; j < PX; j++) ls[j] = nls[j];

        if (k < KK - 1) {
            float vmax = -1.0f; int imax = 0;
            #pragma unroll
            for (int j = 0; j < PX; j++) {
                float pp = ra[j] * expf(nls[j]);
                if (pp > vmax) { vmax = pp; imax = pix + j; }
            }
            unsigned long long key =
                (((unsigned long long)__float_as_uint(vmax)) << 32) |
                (unsigned long long)(unsigned)(16383 - imax);
            publish_argmax(key, &g_slot[(k + 1) * BB + b], s_red, tid);
            grid_sync(gen);         // slot[k+1] final, proceed to next step
        }
    }
}

// ---------------------------------------------------------------------------
// Launch: one cooperative-style kernel, one graph node.
// ---------------------------------------------------------------------------
extern "C" void kernel_launch(void* const* d_in, const int* in_sizes, int n_in,
                              void* d_out, int out_size) {
    const float* features   = (const float*)d_in[0];
    const float* rand_pixel = (const float*)d_in[1];
    const float* conv_w     = (const float*)d_in[2];
    const float* conv_b     = (const float*)d_in[3];
    const float* gate       = (const float*)d_in[4];
    const float* log_sigma  = (const float*)d_in[5];
    const float* uv         = (const float*)d_in[6];
    float* out = (float*)d_out;

    fused_kernel<<<NBLK, NTHR>>>(features, rand_pixel, conv_w, conv_b,
                                 gate, log_sigma, uv, out);
}